// round 1
// baseline (speedup 1.0000x reference)
#include <cuda_runtime.h>
#include <math.h>

#define BN    32      // batch
#define NODES 202
#define NI    200     // items (nodes minus uid,iid)
#define DD    64
#define JT    8       // j's per main block
#define NTILES (NI/JT)   // 25
#define EPS   1e-5f
#define SLOPE 0.01f

// ---------------- device scratch (no allocs allowed) ----------------
__device__ float g_ln[BN * NODES * DD];   // layer-normed embeddings
__device__ float g_ua[BN * NI * DD];      // ua = uid0 * ln(iatt)
__device__ float g_prm[BN * NI * 8];      // per (b,i): q1,m1,iZ1,k1, q2,m2,iZ2,k2
__device__ float g_v[2 * 3 * DD];         // per head: vq,vk,vi (W^T a_x)
__device__ float g_c[2 * 4];              // per head: cq,ck,ci,ab

// ---------------- K0: fold weights ----------------
__global__ void k0_weights(const float* W1, const float* W1b,
                           const float* W2, const float* W2b,
                           const float* a1, const float* a1b,
                           const float* a2, const float* a2b) {
    int t = threadIdx.x;
    for (int idx = t; idx < 2 * 3 * DD; idx += blockDim.x) {
        int h = idx / (3 * DD);
        int r = idx % (3 * DD);
        int vsel = r / DD;           // 0=q,1=k,2=i
        int d = r % DD;
        const float* W = h ? W2 : W1;
        const float* a = (h ? a2 : a1) + vsel * DD;
        float s = 0.f;
        #pragma unroll 8
        for (int o = 0; o < DD; o++) s += a[o] * W[o * DD + d];
        g_v[idx] = s;
    }
    if (t < 8) {
        int h = t >> 2, k = t & 3;
        const float* Wb = h ? W2b : W1b;
        const float* a  = h ? a2  : a1;
        float s;
        if (k < 3) {
            s = 0.f;
            for (int o = 0; o < DD; o++) s += a[k * DD + o] * Wb[o];
        } else {
            s = (h ? a2b : a1b)[0];
        }
        g_c[h * 4 + k] = s;
    }
}

// ---------------- K1: layernorm every (b,node) row ----------------
__global__ void k1_ln(const float* __restrict__ emb,
                      const float* __restrict__ w,
                      const float* __restrict__ bb) {
    int node = blockIdx.x, b = blockIdx.y;
    int d = threadIdx.x;                       // 64 threads
    const float* x = emb + (size_t)(b * NODES + node) * DD;
    float v = x[d];
    __shared__ float red[2];
    float s = v;
    #pragma unroll
    for (int o = 16; o > 0; o >>= 1) s += __shfl_xor_sync(0xffffffffu, s, o);
    if ((d & 31) == 0) red[d >> 5] = s;
    __syncthreads();
    float mu = (red[0] + red[1]) * (1.f / DD);
    __syncthreads();
    float dv = v - mu;
    s = dv * dv;
    #pragma unroll
    for (int o = 16; o > 0; o >>= 1) s += __shfl_xor_sync(0xffffffffu, s, o);
    if ((d & 31) == 0) red[d >> 5] = s;
    __syncthreads();
    float var = (red[0] + red[1]) * (1.f / DD);
    g_ln[(size_t)(b * NODES + node) * DD + d] = dv * rsqrtf(var + EPS) * w[d] + bb[d];
}

// ---------------- K2: per-batch prep (ua, scores, softmax stats, out row0) ----
__global__ void k2_batch(float* __restrict__ out) {
    int b = blockIdx.x;
    int t = threadIdx.x;                       // 256 threads
    __shared__ float uid[DD], iid[DD];
    __shared__ float vq[2][DD], vk[2][DD];
    __shared__ float qc[2], kc[2];
    __shared__ float sk[2][NI];

    if (t < DD) {
        uid[t] = g_ln[(size_t)(b * NODES + 0) * DD + t];
        iid[t] = g_ln[(size_t)(b * NODES + 1) * DD + t];
        vq[0][t] = g_v[0 * 192 + t];       vk[0][t] = g_v[0 * 192 + 64 + t];
        vq[1][t] = g_v[1 * 192 + t];       vk[1][t] = g_v[1 * 192 + 64 + t];
    }
    __syncthreads();

    // ua = uid0 * ln(iatt) -> global
    const float* lnrows = g_ln + (size_t)(b * NODES + 2) * DD;
    float* uarows = g_ua + (size_t)b * NI * DD;
    for (int idx = t; idx < NI * DD; idx += 256)
        uarows[idx] = uid[idx & 63] * lnrows[idx];

    // output row 0: lrelu(uid0 * iid0)
    if (t < DD) {
        float u = uid[t] * iid[t];
        out[(size_t)(b * 201) * DD + t] = u > 0.f ? u : SLOPE * u;
    }
    // per-head additive constants
    if (t < 2) {
        float s = 0.f;
        for (int d = 0; d < DD; d++) s += iid[d] * g_v[t * 192 + 128 + d];
        qc[t] = s + g_c[t * 4 + 2] + g_c[t * 4 + 0] + g_c[t * 4 + 3]; // si(+ci)+cq+ab
        kc[t] = g_c[t * 4 + 1];                                       // ck
    }
    __syncthreads();

    float q1 = 0.f, q2 = 0.f, k1v = 0.f, k2v = 0.f;
    if (t < NI) {
        const float* u = uarows + (size_t)t * DD;
        float s10 = 0, s20 = 0, s11 = 0, s21 = 0;
        #pragma unroll 8
        for (int d = 0; d < DD; d++) {
            float uv = u[d];
            s10 = fmaf(uv, vq[0][d], s10);
            s20 = fmaf(uv, vk[0][d], s20);
            s11 = fmaf(uv, vq[1][d], s11);
            s21 = fmaf(uv, vk[1][d], s21);
        }
        q1 = s10 + qc[0]; k1v = s20 + kc[0];
        q2 = s11 + qc[1]; k2v = s21 + kc[1];
        sk[0][t] = k1v; sk[1][t] = k2v;
    }
    __syncthreads();

    if (t < NI) {
        float m1 = -1e30f, m2 = -1e30f;
        for (int j = 0; j < NI; j++) {
            float s = q1 + sk[0][j]; s = s > 0.f ? s : SLOPE * s; m1 = fmaxf(m1, s);
            float r = q2 + sk[1][j]; r = r > 0.f ? r : SLOPE * r; m2 = fmaxf(m2, r);
        }
        float Z1 = 0.f, Z2 = 0.f;
        for (int j = 0; j < NI; j++) {
            float s = q1 + sk[0][j]; s = s > 0.f ? s : SLOPE * s; Z1 += __expf(s - m1);
            float r = q2 + sk[1][j]; r = r > 0.f ? r : SLOPE * r; Z2 += __expf(r - m2);
        }
        float* p = g_prm + (size_t)(b * NI + t) * 8;
        p[0] = q1; p[1] = m1; p[2] = 1.f / Z1; p[3] = k1v;
        p[4] = q2; p[5] = m2; p[6] = 1.f / Z2; p[7] = k2v;
    }
}

// ---------------- K3: main fused pair kernel ----------------
// smem layout (floats):
//   ua_s[200*65]  13000
//   kk1[200] kk2[200]  400
//   c12[JT*200] float2 = 3200 floats
//   wln[64] bln[64]
//   red[32]  Sc[JT*4=32]
//   part[JT*64] float2 = 1024 floats
#define SMEM_FLOATS (13000 + 400 + 3200 + 128 + 32 + 32 + 1024)
#define SMEM_BYTES  (SMEM_FLOATS * 4)

extern __shared__ float sm3[];

__global__ __launch_bounds__(256, 3)
void k3_main(const float* __restrict__ lnw, const float* __restrict__ lnb,
             float* __restrict__ out) {
    int jt = blockIdx.x;
    int b  = blockIdx.y;
    int t  = threadIdx.x;
    int warp = t >> 5, lane = t & 31;

    float*  ua_s = sm3;                       // 13000
    float*  kk1  = ua_s + 13000;              // 200
    float*  kk2  = kk1 + 200;                 // 200
    float2* c12  = (float2*)(kk2 + 200);      // JT*200 float2
    float*  wln  = (float*)c12 + 2 * JT * NI; // 64
    float*  bln  = wln + 64;                  // 64
    float*  red  = bln + 64;                  // 32
    float*  Sc   = red + 32;                  // 32
    float2* part = (float2*)(Sc + 32);        // JT*64 float2

    const float* uab = g_ua + (size_t)b * NI * DD;
    for (int idx = t; idx < NI * DD; idx += 256)
        ua_s[(idx >> 6) * 65 + (idx & 63)] = uab[idx];
    if (t < 64) { wln[t] = lnw[t]; bln[t] = lnb[t]; }

    float q1 = 0, m1 = 0, iZ1 = 0, q2 = 0, m2 = 0, iZ2 = 0;
    if (t < NI) {
        const float4* p = (const float4*)(g_prm + (size_t)(b * NI + t) * 8);
        float4 p0 = p[0], p1 = p[1];
        q1 = p0.x; m1 = p0.y; iZ1 = p0.z; kk1[t] = p0.w;
        q2 = p1.x; m2 = p1.y; iZ2 = p1.z; kk2[t] = p1.w;
    }
    __syncthreads();

    int jbase = jt * JT;

    // ---- phase 1: per (i,j) pair stats, alpha, c = alpha*r ----
    for (int jj = 0; jj < JT; jj++) {
        int j = jbase + jj;
        float r0 = 0, r1 = 0, r2 = 0, r3 = 0;   // reduction inputs
        if (t < NI) {
            const float* ui = ua_s + t * 65;
            const float* uj = ua_s + j * 65;
            float s1 = 0.f, s2 = 0.f;
            #pragma unroll
            for (int d = 0; d < DD; d++) {
                float p = ui[d] * uj[d];
                s1 += p;
                s2 = fmaf(p, p, s2);
            }
            float mu  = s1 * (1.f / DD);
            float var = fmaf(-mu, mu, s2 * (1.f / DD));
            float rr  = rsqrtf(var + EPS);

            float s = q1 + kk1[j]; s = s > 0.f ? s : SLOPE * s;
            float a1 = __expf(s - m1) * iZ1;
            float c1v = a1 * rr;
            s = q2 + kk2[j]; s = s > 0.f ? s : SLOPE * s;
            float a2 = __expf(s - m2) * iZ2;
            float c2v = a2 * rr;

            c12[jj * NI + t] = make_float2(c1v, c2v);
            r0 = a1; r1 = a2; r2 = c1v * mu; r3 = c2v * mu;
        }
        #pragma unroll
        for (int o = 16; o > 0; o >>= 1) {
            r0 += __shfl_xor_sync(0xffffffffu, r0, o);
            r1 += __shfl_xor_sync(0xffffffffu, r1, o);
            r2 += __shfl_xor_sync(0xffffffffu, r2, o);
            r3 += __shfl_xor_sync(0xffffffffu, r3, o);
        }
        if (lane == 0) {
            red[warp * 4 + 0] = r0; red[warp * 4 + 1] = r1;
            red[warp * 4 + 2] = r2; red[warp * 4 + 3] = r3;
        }
        __syncthreads();
        if (t < 4) {
            float s = 0.f;
            #pragma unroll
            for (int w = 0; w < 8; w++) s += red[w * 4 + t];
            Sc[jj * 4 + t] = s;     // 0:S0_h1 1:S0_h2 2:S2_h1 3:S2_h2
        }
        __syncthreads();
    }

    // ---- phase 2: S1[j,d] = sum_i c_i * ua_i[d], register-tiled over JT ----
    float acc1[JT], acc2[JT];
    #pragma unroll
    for (int jj = 0; jj < JT; jj++) { acc1[jj] = 0.f; acc2[jj] = 0.f; }
    int half = t >> 6, d = t & 63;
    if (t < 128) {
        int i0 = half * (NI / 2), i1 = i0 + (NI / 2);
        for (int i = i0; i < i1; i++) {
            float u = ua_s[i * 65 + d];
            #pragma unroll
            for (int jj = 0; jj < JT; jj++) {
                float2 c = c12[jj * NI + i];
                acc1[jj] = fmaf(c.x, u, acc1[jj]);
                acc2[jj] = fmaf(c.y, u, acc2[jj]);
            }
        }
        if (half == 1) {
            #pragma unroll
            for (int jj = 0; jj < JT; jj++)
                part[jj * 64 + d] = make_float2(acc1[jj], acc2[jj]);
        }
    }
    __syncthreads();

    if (t < 64) {
        #pragma unroll
        for (int jj = 0; jj < JT; jj++) {
            float2 pr = part[jj * 64 + d];
            float S1a = acc1[jj] + pr.x;
            float S1b = acc2[jj] + pr.y;
            int j = jbase + jj;
            float uj = ua_s[j * 65 + d];
            float att1 = wln[d] * (uj * S1a - Sc[jj * 4 + 2]) + bln[d] * Sc[jj * 4 + 0];
            float att2 = wln[d] * (uj * S1b - Sc[jj * 4 + 3]) + bln[d] * Sc[jj * 4 + 1];
            float o = 0.5f * (att1 + att2);
            out[(size_t)(b * 201 + 1 + j) * DD + d] = o > 0.f ? o : SLOPE * o;
        }
    }
}

// ---------------- launch ----------------
extern "C" void kernel_launch(void* const* d_in, const int* in_sizes, int n_in,
                              void* d_out, int out_size) {
    const float* emb = (const float*)d_in[0];
    const float* lnw = (const float*)d_in[1];
    const float* lnb = (const float*)d_in[2];
    const float* W1  = (const float*)d_in[3];
    const float* W1b = (const float*)d_in[4];
    const float* W2  = (const float*)d_in[5];
    const float* W2b = (const float*)d_in[6];
    const float* a1  = (const float*)d_in[7];
    const float* a1b = (const float*)d_in[8];
    const float* a2  = (const float*)d_in[9];
    const float* a2b = (const float*)d_in[10];
    float* out = (float*)d_out;

    (void)in_sizes; (void)n_in; (void)out_size;

    cudaFuncSetAttribute(k3_main, cudaFuncAttributeMaxDynamicSharedMemorySize, SMEM_BYTES);

    k0_weights<<<1, 128>>>(W1, W1b, W2, W2b, a1, a1b, a2, a2b);
    dim3 g1(NODES, BN);
    k1_ln<<<g1, 64>>>(emb, lnw, lnb);
    k2_batch<<<BN, 256>>>(out);
    dim3 g3(NTILES, BN);
    k3_main<<<g3, 256, SMEM_BYTES>>>(lnw, lnb, out);
}

// round 2
// speedup vs baseline: 1.6952x; 1.6952x over previous
#include <cuda_runtime.h>
#include <math.h>

#define BN    32
#define NODES 202
#define NI    200
#define DD    64
#define JT    8
#define NTILES (NI/JT)   // 25
#define EPS   1e-5f
#define SLOPE 0.01f

typedef unsigned long long u64;

// ---- packed fp32x2 helpers (sm_103a) ----
__device__ __forceinline__ u64 f2_mul(u64 a, u64 b) {
    u64 r; asm("mul.rn.f32x2 %0,%1,%2;" : "=l"(r) : "l"(a), "l"(b)); return r;
}
__device__ __forceinline__ u64 f2_add(u64 a, u64 b) {
    u64 r; asm("add.rn.f32x2 %0,%1,%2;" : "=l"(r) : "l"(a), "l"(b)); return r;
}
__device__ __forceinline__ u64 f2_fma(u64 a, u64 b, u64 c) {
    u64 r; asm("fma.rn.f32x2 %0,%1,%2,%3;" : "=l"(r) : "l"(a), "l"(b), "l"(c)); return r;
}
__device__ __forceinline__ u64 f2_pack(float lo, float hi) {
    u64 r; asm("mov.b64 %0,{%1,%2};" : "=l"(r) : "f"(lo), "f"(hi)); return r;
}
__device__ __forceinline__ void f2_unpack(u64 v, float& lo, float& hi) {
    asm("mov.b64 {%0,%1},%2;" : "=f"(lo), "=f"(hi) : "l"(v));
}

// ---------------- device scratch ----------------
__device__ float g_ln[BN * NODES * DD];
__device__ float g_ua[BN * NI * DD];
__device__ float g_prm[BN * NI * 8];     // (q1,k1,iZ1,q2),(k2,iZ2,_,_)
__device__ float g_v[2 * 3 * DD];        // per head: vq,vk,vi
__device__ float g_c[2 * 4];             // per head: cq,ck,ci,ab

// ---------------- K1: warp-per-row LN  (+ weight folding on last block) ----
__global__ void k1_ln(const float* __restrict__ emb,
                      const float* __restrict__ w,
                      const float* __restrict__ bb,
                      const float* __restrict__ W1, const float* __restrict__ W1b,
                      const float* __restrict__ W2, const float* __restrict__ W2b,
                      const float* __restrict__ a1, const float* __restrict__ a1b,
                      const float* __restrict__ a2, const float* __restrict__ a2b) {
    int t = threadIdx.x;
    if (blockIdx.x == (BN * NODES) / 8) {
        // weight folding: g_v[h][sel][d] = sum_o a[h][sel*64+o] * W[h][o][d]
        for (int idx = t; idx < 2 * 3 * DD; idx += blockDim.x) {
            int h = idx / (3 * DD);
            int r = idx % (3 * DD);
            int vsel = r / DD, d = r % DD;
            const float* W = h ? W2 : W1;
            const float* a = (h ? a2 : a1) + vsel * DD;
            float s = 0.f;
            #pragma unroll 8
            for (int o = 0; o < DD; o++) s = fmaf(a[o], W[o * DD + d], s);
            g_v[idx] = s;
        }
        if (t < 8) {
            int h = t >> 2, k = t & 3;
            const float* Wb = h ? W2b : W1b;
            const float* a  = h ? a2  : a1;
            float s;
            if (k < 3) {
                s = 0.f;
                for (int o = 0; o < DD; o++) s = fmaf(a[k * DD + o], Wb[o], s);
            } else {
                s = (h ? a2b : a1b)[0];
            }
            g_c[h * 4 + k] = s;
        }
        return;
    }
    int lane = t & 31;
    int row = blockIdx.x * 8 + (t >> 5);
    const float* x = emb + (size_t)row * DD;
    float a = x[lane], b2 = x[lane + 32];
    float s = a + b2;
    #pragma unroll
    for (int o = 16; o > 0; o >>= 1) s += __shfl_xor_sync(0xffffffffu, s, o);
    float mu = s * (1.f / DD);
    float da = a - mu, db = b2 - mu;
    float q = fmaf(da, da, db * db);
    #pragma unroll
    for (int o = 16; o > 0; o >>= 1) q += __shfl_xor_sync(0xffffffffu, q, o);
    float rs = rsqrtf(q * (1.f / DD) + EPS);
    g_ln[(size_t)row * DD + lane]      = fmaf(da * rs, w[lane],      bb[lane]);
    g_ln[(size_t)row * DD + lane + 32] = fmaf(db * rs, w[lane + 32], bb[lane + 32]);
}

// ---------------- K2: per-batch prep ----------------
__global__ void k2_batch(float* __restrict__ out) {
    int b = blockIdx.x;
    int t = threadIdx.x;   // 256
    __shared__ __align__(16) float uid[DD], iid[DD];
    __shared__ float vq[2][DD], vk[2][DD];
    __shared__ float qc[2], kc[2];
    __shared__ float sk[2][NI];

    if (t < DD) {
        uid[t] = g_ln[(size_t)(b * NODES + 0) * DD + t];
        iid[t] = g_ln[(size_t)(b * NODES + 1) * DD + t];
        vq[0][t] = g_v[t];        vk[0][t] = g_v[64 + t];
        vq[1][t] = g_v[192 + t];  vk[1][t] = g_v[192 + 64 + t];
    }
    __syncthreads();

    // ua = uid * ln(iatt)  (float4)
    const float4* ln4 = (const float4*)(g_ln + (size_t)(b * NODES + 2) * DD);
    float4* ua4 = (float4*)(g_ua + (size_t)b * NI * DD);
    const float4* uid4 = (const float4*)uid;
    for (int idx = t; idx < NI * DD / 4; idx += 256) {
        float4 u = uid4[idx & 15], l = ln4[idx];
        ua4[idx] = make_float4(u.x * l.x, u.y * l.y, u.z * l.z, u.w * l.w);
    }

    if (t < DD) {
        float u = uid[t] * iid[t];
        out[(size_t)(b * 201) * DD + t] = u > 0.f ? u : SLOPE * u;
    }
    if (t < 2) {
        float s = 0.f;
        for (int d = 0; d < DD; d++) s = fmaf(iid[d], g_v[t * 192 + 128 + d], s);
        qc[t] = s + g_c[t * 4 + 2] + g_c[t * 4 + 0] + g_c[t * 4 + 3];
        kc[t] = g_c[t * 4 + 1];
    }
    __syncthreads();

    float q1 = 0.f, q2 = 0.f, k1v = 0.f, k2v = 0.f;
    if (t < NI) {
        const float4* u4 = (const float4*)(g_ua + ((size_t)b * NI + t) * DD);
        float s10 = 0, s20 = 0, s11 = 0, s21 = 0;
        #pragma unroll
        for (int c = 0; c < 16; c++) {
            float4 u = u4[c];
            int d = c * 4;
            s10 = fmaf(u.x, vq[0][d], fmaf(u.y, vq[0][d+1], fmaf(u.z, vq[0][d+2], fmaf(u.w, vq[0][d+3], s10))));
            s20 = fmaf(u.x, vk[0][d], fmaf(u.y, vk[0][d+1], fmaf(u.z, vk[0][d+2], fmaf(u.w, vk[0][d+3], s20))));
            s11 = fmaf(u.x, vq[1][d], fmaf(u.y, vq[1][d+1], fmaf(u.z, vq[1][d+2], fmaf(u.w, vq[1][d+3], s11))));
            s21 = fmaf(u.x, vk[1][d], fmaf(u.y, vk[1][d+1], fmaf(u.z, vk[1][d+2], fmaf(u.w, vk[1][d+3], s21))));
        }
        q1 = s10 + qc[0]; k1v = s20 + kc[0];
        q2 = s11 + qc[1]; k2v = s21 + kc[1];
        sk[0][t] = k1v; sk[1][t] = k2v;
    }
    __syncthreads();

    if (t < NI) {
        float Z1 = 0.f, Z2 = 0.f;
        for (int j = 0; j < NI; j++) {
            float s = q1 + sk[0][j]; s = s > 0.f ? s : SLOPE * s; Z1 += __expf(s);
            float r = q2 + sk[1][j]; r = r > 0.f ? r : SLOPE * r; Z2 += __expf(r);
        }
        float4* p = (float4*)(g_prm + (size_t)(b * NI + t) * 8);
        p[0] = make_float4(q1, k1v, 1.f / Z1, q2);
        p[1] = make_float4(k2v, 1.f / Z2, 0.f, 0.f);
    }
}

// ---------------- K3: main fused pair kernel ----------------
// smem floats: ua_s[200*68]=13600 | kk1[200] kk2[200] | c12[200*20]=4000
//              wln[64] bln[64] | Sc[32] | part[JT*64*2]=1024 (red aliased)
#define OFF_UA   0
#define OFF_KK1  13600
#define OFF_KK2  13800
#define OFF_C12  14000
#define OFF_WLN  18000
#define OFF_BLN  18064
#define OFF_SC   18128
#define OFF_PART 18160
#define SMEM_FLOATS (OFF_PART + JT * DD * 2)   // 19184
#define SMEM_BYTES  (SMEM_FLOATS * 4)

extern __shared__ float sm3[];

__global__ __launch_bounds__(256, 3)
void k3_main(const float* __restrict__ lnw, const float* __restrict__ lnb,
             float* __restrict__ out) {
    int jt = blockIdx.x;
    int b  = blockIdx.y;
    int t  = threadIdx.x;
    int warp = t >> 5, lane = t & 31;

    float* ua_s = sm3 + OFF_UA;     // row stride 68
    float* kk1  = sm3 + OFF_KK1;
    float* kk2  = sm3 + OFF_KK2;
    float* c12  = sm3 + OFF_C12;    // row stride 20, [i][jj*2+h]
    float* wln  = sm3 + OFF_WLN;
    float* bln  = sm3 + OFF_BLN;
    float* Sc   = sm3 + OFF_SC;
    float* part = sm3 + OFF_PART;   // u64-viewed [jj*64+d]
    float* red  = part;             // alias (used before part writes)

    // stage ua tile (float4, padded rows)
    const float4* uab4 = (const float4*)(g_ua + (size_t)b * NI * DD);
    for (int idx = t; idx < NI * 16; idx += 256) {
        int i = idx >> 4, c = idx & 15;
        *(float4*)(ua_s + i * 68 + c * 4) = uab4[idx];
    }
    if (t < 64) { wln[t] = lnw[t]; bln[t] = lnb[t]; }

    float q1 = 0, iZ1 = 0, q2 = 0, iZ2 = 0;
    if (t < NI) {
        const float4* pp = (const float4*)(g_prm + (size_t)(b * NI + t) * 8);
        float4 p0 = pp[0], p1 = pp[1];
        q1 = p0.x; kk1[t] = p0.y; iZ1 = p0.z; q2 = p0.w;
        kk2[t] = p1.x; iZ2 = p1.y;
    }
    __syncthreads();

    int jbase = jt * JT;

    // ---- phase 1: Gram stats via packed f32x2, d-outer / j-register-tiled ----
    u64 s1p[JT], s2p[JT];
    #pragma unroll
    for (int jj = 0; jj < JT; jj++) { s1p[jj] = 0ull; s2p[jj] = 0ull; }

    if (t < NI) {
        const float* ui = ua_s + t * 68;
        const float* ujb = ua_s + jbase * 68;
        #pragma unroll 4
        for (int dc = 0; dc < 16; dc++) {
            ulonglong2 u = *(const ulonglong2*)(ui + dc * 4);
            #pragma unroll
            for (int jj = 0; jj < JT; jj++) {
                ulonglong2 v = *(const ulonglong2*)(ujb + jj * 68 + dc * 4);  // broadcast
                u64 p0 = f2_mul(u.x, v.x);
                u64 p1 = f2_mul(u.y, v.y);
                s1p[jj] = f2_add(s1p[jj], p0);
                s1p[jj] = f2_add(s1p[jj], p1);
                s2p[jj] = f2_fma(p0, p0, s2p[jj]);
                s2p[jj] = f2_fma(p1, p1, s2p[jj]);
            }
        }
    }

    // per-jj epilogue: alpha, c = alpha*rr; stage c-stores; reduction inputs
    float ra[JT], rb[JT], rc[JT], rd[JT];
    float cst[2 * JT];
    if (t < NI) {
        #pragma unroll
        for (int jj = 0; jj < JT; jj++) {
            float l1, h1, l2, h2;
            f2_unpack(s1p[jj], l1, h1);
            f2_unpack(s2p[jj], l2, h2);
            float mu  = (l1 + h1) * (1.f / DD);
            float var = fmaf(-mu, mu, (l2 + h2) * (1.f / DD));
            float rr  = rsqrtf(var + EPS);
            int j = jbase + jj;
            float s = q1 + kk1[j]; s = s > 0.f ? s : SLOPE * s;
            float a1 = __expf(s) * iZ1;
            float c1 = a1 * rr;
            s = q2 + kk2[j]; s = s > 0.f ? s : SLOPE * s;
            float a2 = __expf(s) * iZ2;
            float c2 = a2 * rr;
            cst[jj * 2 + 0] = c1; cst[jj * 2 + 1] = c2;
            ra[jj] = a1; rb[jj] = a2; rc[jj] = c1 * mu; rd[jj] = c2 * mu;
        }
        float* crow = c12 + t * 20;
        #pragma unroll
        for (int k = 0; k < 4; k++)
            *(float4*)(crow + k * 4) = make_float4(cst[k*4], cst[k*4+1], cst[k*4+2], cst[k*4+3]);
    } else {
        #pragma unroll
        for (int jj = 0; jj < JT; jj++) { ra[jj] = 0; rb[jj] = 0; rc[jj] = 0; rd[jj] = 0; }
    }

    // cross-thread reductions (one pass, no per-jj barriers)
    #pragma unroll
    for (int jj = 0; jj < JT; jj++) {
        float v0 = ra[jj], v1 = rb[jj], v2 = rc[jj], v3 = rd[jj];
        #pragma unroll
        for (int o = 16; o > 0; o >>= 1) {
            v0 += __shfl_xor_sync(0xffffffffu, v0, o);
            v1 += __shfl_xor_sync(0xffffffffu, v1, o);
            v2 += __shfl_xor_sync(0xffffffffu, v2, o);
            v3 += __shfl_xor_sync(0xffffffffu, v3, o);
        }
        if (lane == 0) {
            red[warp * 32 + jj * 4 + 0] = v0;
            red[warp * 32 + jj * 4 + 1] = v1;
            red[warp * 32 + jj * 4 + 2] = v2;
            red[warp * 32 + jj * 4 + 3] = v3;
        }
    }
    __syncthreads();
    if (t < 32) {
        float s = 0.f;
        #pragma unroll
        for (int w = 0; w < 8; w++) s += red[w * 32 + t];
        Sc[t] = s;
    }
    __syncthreads();

    // ---- phase 2: S1[j,d] = sum_i c_i * ua_i[d]  (packed over heads) ----
    u64 acc[JT];
    #pragma unroll
    for (int jj = 0; jj < JT; jj++) acc[jj] = 0ull;
    int half = t >> 6, d = t & 63;
    if (t < 128) {
        int i0 = half * (NI / 2), i1 = i0 + (NI / 2);
        for (int i = i0; i < i1; i++) {
            float u = ua_s[i * 68 + d];
            u64 up = f2_pack(u, u);
            const ulonglong2* cp = (const ulonglong2*)(c12 + i * 20);   // broadcast
            ulonglong2 c0 = cp[0], c1 = cp[1];
            acc[0] = f2_fma(c0.x, up, acc[0]);
            acc[1] = f2_fma(c0.y, up, acc[1]);
            acc[2] = f2_fma(c1.x, up, acc[2]);
            acc[3] = f2_fma(c1.y, up, acc[3]);
            c0 = cp[2]; c1 = cp[3];
            acc[4] = f2_fma(c0.x, up, acc[4]);
            acc[5] = f2_fma(c0.y, up, acc[5]);
            acc[6] = f2_fma(c1.x, up, acc[6]);
            acc[7] = f2_fma(c1.y, up, acc[7]);
        }
        if (half == 1) {
            u64* p64 = (u64*)part;
            #pragma unroll
            for (int jj = 0; jj < JT; jj++) p64[jj * 64 + d] = acc[jj];
        }
    }
    __syncthreads();

    if (t < 64) {
        const u64* p64 = (const u64*)part;
        #pragma unroll
        for (int jj = 0; jj < JT; jj++) {
            u64 tot = f2_add(acc[jj], p64[jj * 64 + d]);
            float S1a, S1b;
            f2_unpack(tot, S1a, S1b);
            int j = jbase + jj;
            float uj = ua_s[j * 68 + d];
            float att1 = fmaf(wln[d], fmaf(uj, S1a, -Sc[jj * 4 + 2]), bln[d] * Sc[jj * 4 + 0]);
            float att2 = fmaf(wln[d], fmaf(uj, S1b, -Sc[jj * 4 + 3]), bln[d] * Sc[jj * 4 + 1]);
            float o = 0.5f * (att1 + att2);
            out[(size_t)(b * 201 + 1 + j) * DD + d] = o > 0.f ? o : SLOPE * o;
        }
    }
}

// ---------------- launch ----------------
extern "C" void kernel_launch(void* const* d_in, const int* in_sizes, int n_in,
                              void* d_out, int out_size) {
    const float* emb = (const float*)d_in[0];
    const float* lnw = (const float*)d_in[1];
    const float* lnb = (const float*)d_in[2];
    const float* W1  = (const float*)d_in[3];
    const float* W1b = (const float*)d_in[4];
    const float* W2  = (const float*)d_in[5];
    const float* W2b = (const float*)d_in[6];
    const float* a1  = (const float*)d_in[7];
    const float* a1b = (const float*)d_in[8];
    const float* a2  = (const float*)d_in[9];
    const float* a2b = (const float*)d_in[10];
    float* out = (float*)d_out;
    (void)in_sizes; (void)n_in; (void)out_size;

    cudaFuncSetAttribute(k3_main, cudaFuncAttributeMaxDynamicSharedMemorySize, SMEM_BYTES);

    k1_ln<<<(BN * NODES) / 8 + 1, 256>>>(emb, lnw, lnb,
                                         W1, W1b, W2, W2b, a1, a1b, a2, a2b);
    k2_batch<<<BN, 256>>>(out);
    dim3 g3(NTILES, BN);
    k3_main<<<g3, 256, SMEM_BYTES>>>(lnw, lnb, out);
}